// round 14
// baseline (speedup 1.0000x reference)
#include <cuda_runtime.h>
#include <cuda_bf16.h>
#include <cstdint>
#include <cstddef>

// Problem constants
#define NB   4
#define TCTX 4096
#define DEMB 512
#define SCALE 0.125f   // 1/sqrt(512/8) = 1/8

static constexpr size_t QKV_ELEMS = (size_t)NB * TCTX * DEMB;   // 8,388,608
static constexpr size_t ATT_ELEMS = (size_t)NB * TCTX * TCTX;   // 67,108,864

// Scratch (static __device__ arrays — allocation-free per harness rules)
__device__ __align__(128) __nv_bfloat16 g_Qh[QKV_ELEMS];
__device__ __align__(128) __nv_bfloat16 g_Ql[QKV_ELEMS];
__device__ __align__(128) __nv_bfloat16 g_Kh[QKV_ELEMS];
__device__ __align__(128) __nv_bfloat16 g_Kl[QKV_ELEMS];
__device__ __align__(128) __nv_bfloat16 g_Vth[QKV_ELEMS];   // V transposed [b][d][s]
__device__ __align__(128) __nv_bfloat16 g_Vtl[QKV_ELEMS];
__device__ __align__(128) float         g_S [ATT_ELEMS];    // logits (unscaled)
__device__ __align__(128) __nv_bfloat16 g_Ph[ATT_ELEMS];    // softmax probs hi
__device__ __align__(128) __nv_bfloat16 g_Pl[ATT_ELEMS];    // softmax probs lo

// ---------------------------------------------------------------------------
// PTX helpers
// ---------------------------------------------------------------------------
__device__ __forceinline__ void cp16(void* dst_smem, const void* src_gmem) {
    uint32_t d = (uint32_t)__cvta_generic_to_shared(dst_smem);
    size_t   s = __cvta_generic_to_global(src_gmem);
    asm volatile("cp.async.cg.shared.global [%0], [%1], 16;" :: "r"(d), "l"(s) : "memory");
}
__device__ __forceinline__ void cp_commit() {
    asm volatile("cp.async.commit_group;" ::: "memory");
}
__device__ __forceinline__ void cp_wait1() {
    asm volatile("cp.async.wait_group 1;" ::: "memory");
}
__device__ __forceinline__ void cp_wait0() {
    asm volatile("cp.async.wait_group 0;" ::: "memory");
}
__device__ __forceinline__ void ldsm4(uint32_t& r0, uint32_t& r1, uint32_t& r2, uint32_t& r3,
                                      const void* p) {
    uint32_t a = (uint32_t)__cvta_generic_to_shared((void*)p);
    asm volatile("ldmatrix.sync.aligned.m8n8.x4.shared.b16 {%0,%1,%2,%3}, [%4];"
                 : "=r"(r0), "=r"(r1), "=r"(r2), "=r"(r3) : "r"(a));
}
__device__ __forceinline__ void mma16816(float* d, const uint32_t* a, const uint32_t* b) {
    asm volatile("mma.sync.aligned.m16n8k16.row.col.f32.bf16.bf16.f32 "
                 "{%0,%1,%2,%3}, {%4,%5,%6,%7}, {%8,%9}, {%0,%1,%2,%3};"
                 : "+f"(d[0]), "+f"(d[1]), "+f"(d[2]), "+f"(d[3])
                 : "r"(a[0]), "r"(a[1]), "r"(a[2]), "r"(a[3]), "r"(b[0]), "r"(b[1]));
}

// ---------------------------------------------------------------------------
// Prep 1: fp32 -> bf16 hi/lo split (elementwise)
// ---------------------------------------------------------------------------
__global__ void __launch_bounds__(256) split_kernel(const float* __restrict__ x,
                                                    __nv_bfloat16* __restrict__ hi,
                                                    __nv_bfloat16* __restrict__ lo) {
    size_t i = (size_t)blockIdx.x * 256 + threadIdx.x;
    float v = x[i];
    __nv_bfloat16 h = __float2bfloat16(v);
    hi[i] = h;
    lo[i] = __float2bfloat16(v - __bfloat162float(h));
}

// ---------------------------------------------------------------------------
// Prep 2: transpose V [b][s][d] -> Vt [b][d][s], with hi/lo split
// ---------------------------------------------------------------------------
__global__ void __launch_bounds__(256) vtrans_split(const float* __restrict__ V,
                                                    __nv_bfloat16* __restrict__ th,
                                                    __nv_bfloat16* __restrict__ tl) {
    __shared__ float tile[32][33];
    int b = blockIdx.z;
    int s0 = blockIdx.x * 32;
    int d0 = blockIdx.y * 32;
    int tx = threadIdx.x, ty = threadIdx.y;
    const float* Vb = V + (size_t)b * TCTX * DEMB;
#pragma unroll
    for (int i = ty; i < 32; i += 8)
        tile[i][tx] = Vb[(size_t)(s0 + i) * DEMB + d0 + tx];
    __syncthreads();
    size_t base = (size_t)b * DEMB * TCTX;
#pragma unroll
    for (int i = ty; i < 32; i += 8) {
        float v = tile[tx][i];                       // = V[s0+tx][d0+i]
        size_t o = base + (size_t)(d0 + i) * TCTX + s0 + tx;
        __nv_bfloat16 h = __float2bfloat16(v);
        th[o] = h;
        tl[o] = __float2bfloat16(v - __bfloat162float(h));
    }
}

// ---------------------------------------------------------------------------
// GEMM (NT, bf16x3 -> fp32): C[m,n] = sum_k A[m,k]*B[n,k]
// A,B stored row-major over k (lda = ldb = K). Used for both Q·K^T and P·V(t).
// CTA tile 128x128, warps 2x4 (64x32 each), K-stage 32, double-buffered cp.async.
// ---------------------------------------------------------------------------
#define BM 128
#define BN 128
#define BK 32
#define SLD 40                 // padded smem row stride (bf16 elems): conflict-free ldmatrix
#define TILE_ELEMS (128 * SLD) // 5120
#define GEMM_SMEM_BYTES (2 * 4 * TILE_ELEMS * 2)  // 81,920

__global__ void __launch_bounds__(256, 1) gemm_nt_x3(
    const __nv_bfloat16* __restrict__ Ah, const __nv_bfloat16* __restrict__ Al,
    const __nv_bfloat16* __restrict__ Bh, const __nv_bfloat16* __restrict__ Bl,
    float* __restrict__ C,
    int K, int ldc, size_t sAb, size_t sBb, size_t sCb)
{
    extern __shared__ __nv_bfloat16 sm[];
    // per stage layout: [Ah | Al | Bh | Bl], each TILE_ELEMS
    int tid  = threadIdx.x;
    int lane = tid & 31;
    int w    = tid >> 5;
    int wm   = w >> 2;   // 0..1
    int wn   = w & 3;    // 0..3

    const __nv_bfloat16* gAh = Ah + (size_t)blockIdx.z * sAb + (size_t)(blockIdx.y * BM) * K;
    const __nv_bfloat16* gAl = Al + (size_t)blockIdx.z * sAb + (size_t)(blockIdx.y * BM) * K;
    const __nv_bfloat16* gBh = Bh + (size_t)blockIdx.z * sBb + (size_t)(blockIdx.x * BN) * K;
    const __nv_bfloat16* gBl = Bl + (size_t)blockIdx.z * sBb + (size_t)(blockIdx.x * BN) * K;

    float acc[4][4][4];
#pragma unroll
    for (int i = 0; i < 4; i++)
#pragma unroll
        for (int j = 0; j < 4; j++)
#pragma unroll
            for (int r = 0; r < 4; r++) acc[i][j][r] = 0.f;

    auto load = [&](int stage, int k0) {
        __nv_bfloat16* base = sm + stage * 4 * TILE_ELEMS;
#pragma unroll
        for (int i = 0; i < 2; i++) {
            int c   = tid + i * 256;      // 512 chunks of 16B per 128x32 tile
            int row = c >> 2;
            int cc  = (c & 3) << 3;       // bf16 col offset (8 elems = 16B)
            size_t g = (size_t)row * K + k0 + cc;
            int    s = row * SLD + cc;
            cp16(base + s,                  gAh + g);
            cp16(base + TILE_ELEMS + s,     gAl + g);
            cp16(base + 2 * TILE_ELEMS + s, gBh + g);
            cp16(base + 3 * TILE_ELEMS + s, gBl + g);
        }
        cp_commit();
    };

    load(0, 0);
    int nk = K / BK;
    for (int ko = 0; ko < nk; ko++) {
        int cur = ko & 1;
        if (ko + 1 < nk) { load(cur ^ 1, (ko + 1) * BK); cp_wait1(); }
        else             { cp_wait0(); }
        __syncthreads();

        const __nv_bfloat16* sAh = sm + cur * 4 * TILE_ELEMS;
        const __nv_bfloat16* sAl = sAh + TILE_ELEMS;
        const __nv_bfloat16* sBh = sAh + 2 * TILE_ELEMS;
        const __nv_bfloat16* sBl = sAh + 3 * TILE_ELEMS;

#pragma unroll
        for (int kk = 0; kk < 2; kk++) {
            int g    = lane >> 3;
            int r    = lane & 7;
            int frow = r + (g & 1) * 8;
            int fcol = ((g >> 1) << 3) + kk * 16;

            uint32_t ah[4][4], al[4][4];
#pragma unroll
            for (int mt = 0; mt < 4; mt++) {
                int off = (wm * 64 + mt * 16 + frow) * SLD + fcol;
                ldsm4(ah[mt][0], ah[mt][1], ah[mt][2], ah[mt][3], sAh + off);
                ldsm4(al[mt][0], al[mt][1], al[mt][2], al[mt][3], sAl + off);
            }
            uint32_t bh[4][2], bl[4][2];
#pragma unroll
            for (int np = 0; np < 2; np++) {
                int off = (wn * 32 + np * 16 + frow) * SLD + fcol;
                uint32_t r0, r1, r2, r3;
                ldsm4(r0, r1, r2, r3, sBh + off);
                bh[np * 2][0] = r0; bh[np * 2][1] = r2;
                bh[np * 2 + 1][0] = r1; bh[np * 2 + 1][1] = r3;
                ldsm4(r0, r1, r2, r3, sBl + off);
                bl[np * 2][0] = r0; bl[np * 2][1] = r2;
                bl[np * 2 + 1][0] = r1; bl[np * 2 + 1][1] = r3;
            }
#pragma unroll
            for (int mt = 0; mt < 4; mt++)
#pragma unroll
                for (int nt = 0; nt < 4; nt++) {
                    mma16816(acc[mt][nt], ah[mt], bh[nt]);   // hi*hi
                    mma16816(acc[mt][nt], ah[mt], bl[nt]);   // hi*lo
                    mma16816(acc[mt][nt], al[mt], bh[nt]);   // lo*hi
                }
        }
        __syncthreads();
    }

    float* Cb = C + (size_t)blockIdx.z * sCb;
    int mb = blockIdx.y * BM + wm * 64;
    int nb = blockIdx.x * BN + wn * 32;
#pragma unroll
    for (int mt = 0; mt < 4; mt++) {
        int row = mb + mt * 16 + (lane >> 2);
#pragma unroll
        for (int nt = 0; nt < 4; nt++) {
            int col = nb + nt * 8 + ((lane & 3) << 1);
            float2 v0; v0.x = acc[mt][nt][0]; v0.y = acc[mt][nt][1];
            float2 v1; v1.x = acc[mt][nt][2]; v1.y = acc[mt][nt][3];
            *(float2*)(Cb + (size_t)row * ldc + col)       = v0;
            *(float2*)(Cb + (size_t)(row + 8) * ldc + col) = v1;
        }
    }
}

// ---------------------------------------------------------------------------
// Softmax over rows of S (scale applied here), output hi/lo bf16 probs
// One CTA (256 threads) per row of 4096.
// ---------------------------------------------------------------------------
__global__ void __launch_bounds__(256) softmax_kernel(const float* __restrict__ S,
                                                      __nv_bfloat16* __restrict__ Ph,
                                                      __nv_bfloat16* __restrict__ Pl) {
    __shared__ float redm[8], reds[8];
    size_t row = blockIdx.x;
    const float* s = S + row * (size_t)TCTX;
    int tid = threadIdx.x;

    float x[16];
    float m = -1e30f;
#pragma unroll
    for (int i = 0; i < 16; i++) {
        x[i] = s[tid + (i << 8)] * SCALE;
        m = fmaxf(m, x[i]);
    }
#pragma unroll
    for (int o = 16; o > 0; o >>= 1) m = fmaxf(m, __shfl_xor_sync(0xffffffffu, m, o));
    if ((tid & 31) == 0) redm[tid >> 5] = m;
    __syncthreads();
    float M = redm[0];
#pragma unroll
    for (int i = 1; i < 8; i++) M = fmaxf(M, redm[i]);

    float sum = 0.f;
#pragma unroll
    for (int i = 0; i < 16; i++) { x[i] = __expf(x[i] - M); sum += x[i]; }
#pragma unroll
    for (int o = 16; o > 0; o >>= 1) sum += __shfl_xor_sync(0xffffffffu, sum, o);
    if ((tid & 31) == 0) reds[tid >> 5] = sum;
    __syncthreads();
    float tot = 0.f;
#pragma unroll
    for (int i = 0; i < 8; i++) tot += reds[i];
    float inv = 1.f / tot;

    __nv_bfloat16* ph = Ph + row * (size_t)TCTX;
    __nv_bfloat16* pl = Pl + row * (size_t)TCTX;
#pragma unroll
    for (int i = 0; i < 16; i++) {
        float p = x[i] * inv;
        __nv_bfloat16 h = __float2bfloat16(p);
        ph[tid + (i << 8)] = h;
        pl[tid + (i << 8)] = __float2bfloat16(p - __bfloat162float(h));
    }
}

// ---------------------------------------------------------------------------
// Launch
// ---------------------------------------------------------------------------
extern "C" void kernel_launch(void* const* d_in, const int* in_sizes, int n_in,
                              void* d_out, int out_size) {
    const float* q = (const float*)d_in[0];
    const float* k = (const float*)d_in[1];
    const float* v = (const float*)d_in[2];
    float* out = (float*)d_out;

    __nv_bfloat16 *Qh, *Ql, *Kh, *Kl, *Vth, *Vtl, *Ph, *Pl;
    float* S;
    cudaGetSymbolAddress((void**)&Qh,  g_Qh);
    cudaGetSymbolAddress((void**)&Ql,  g_Ql);
    cudaGetSymbolAddress((void**)&Kh,  g_Kh);
    cudaGetSymbolAddress((void**)&Kl,  g_Kl);
    cudaGetSymbolAddress((void**)&Vth, g_Vth);
    cudaGetSymbolAddress((void**)&Vtl, g_Vtl);
    cudaGetSymbolAddress((void**)&S,   g_S);
    cudaGetSymbolAddress((void**)&Ph,  g_Ph);
    cudaGetSymbolAddress((void**)&Pl,  g_Pl);

    cudaFuncSetAttribute(gemm_nt_x3, cudaFuncAttributeMaxDynamicSharedMemorySize,
                         GEMM_SMEM_BYTES);

    // Prep: split Q, K; transpose+split V
    int nblk = (int)(QKV_ELEMS / 256);
    split_kernel<<<nblk, 256>>>(q, Qh, Ql);
    split_kernel<<<nblk, 256>>>(k, Kh, Kl);
    vtrans_split<<<dim3(TCTX / 32, DEMB / 32, NB), dim3(32, 8)>>>(v, Vth, Vtl);

    // GEMM1: S[b] = Q[b] * K[b]^T   (M=N=4096, K=512)
    gemm_nt_x3<<<dim3(TCTX / BN, TCTX / BM, NB), 256, GEMM_SMEM_BYTES>>>(
        Qh, Ql, Kh, Kl, S,
        DEMB, TCTX,
        (size_t)TCTX * DEMB, (size_t)TCTX * DEMB, (size_t)TCTX * TCTX);

    // Softmax rows -> P hi/lo
    softmax_kernel<<<NB * TCTX, 256>>>(S, Ph, Pl);

    // GEMM2: O[b] = P[b] * V[b]    (M=4096, N=512, K=4096; B = V^T rows = d)
    gemm_nt_x3<<<dim3(DEMB / BN, TCTX / BM, NB), 256, GEMM_SMEM_BYTES>>>(
        Ph, Pl, Vth, Vtl, out,
        TCTX, DEMB,
        (size_t)TCTX * TCTX, (size_t)DEMB * TCTX, (size_t)TCTX * DEMB);
}

// round 16
// speedup vs baseline: 1.1133x; 1.1133x over previous
#include <cuda_runtime.h>
#include <cuda_bf16.h>
#include <cstdint>
#include <cstddef>

// Problem constants
#define NB   4
#define TCTX 4096
#define DEMB 512
#define SCALE 0.125f   // 1/sqrt(512/8) = 1/8

static constexpr size_t QKV_ELEMS = (size_t)NB * TCTX * DEMB;   // 8,388,608
static constexpr size_t ATT_ELEMS = (size_t)NB * TCTX * TCTX;   // 67,108,864

// Scratch (static __device__ arrays — allocation-free per harness rules)
__device__ __align__(128) __nv_bfloat16 g_Qh[QKV_ELEMS];
__device__ __align__(128) __nv_bfloat16 g_Ql[QKV_ELEMS];
__device__ __align__(128) __nv_bfloat16 g_Kh[QKV_ELEMS];
__device__ __align__(128) __nv_bfloat16 g_Kl[QKV_ELEMS];
__device__ __align__(128) __nv_bfloat16 g_Vth[QKV_ELEMS];   // V transposed [b][d][s]
__device__ __align__(128) __nv_bfloat16 g_Vtl[QKV_ELEMS];
__device__ __align__(128) float         g_S [ATT_ELEMS];    // logits (unscaled)
__device__ __align__(128) __nv_bfloat16 g_Ph[ATT_ELEMS];    // softmax probs hi
__device__ __align__(128) __nv_bfloat16 g_Pl[ATT_ELEMS];    // softmax probs lo

// ---------------------------------------------------------------------------
// PTX helpers
// ---------------------------------------------------------------------------
__device__ __forceinline__ void cp16(void* dst_smem, const void* src_gmem) {
    uint32_t d = (uint32_t)__cvta_generic_to_shared(dst_smem);
    size_t   s = __cvta_generic_to_global(src_gmem);
    asm volatile("cp.async.cg.shared.global [%0], [%1], 16;" :: "r"(d), "l"(s) : "memory");
}
__device__ __forceinline__ void cp_commit() {
    asm volatile("cp.async.commit_group;" ::: "memory");
}
__device__ __forceinline__ void cp_wait1() {
    asm volatile("cp.async.wait_group 1;" ::: "memory");
}
__device__ __forceinline__ void cp_wait0() {
    asm volatile("cp.async.wait_group 0;" ::: "memory");
}
__device__ __forceinline__ void ldsm4(uint32_t& r0, uint32_t& r1, uint32_t& r2, uint32_t& r3,
                                      const void* p) {
    uint32_t a = (uint32_t)__cvta_generic_to_shared((void*)p);
    asm volatile("ldmatrix.sync.aligned.m8n8.x4.shared.b16 {%0,%1,%2,%3}, [%4];"
                 : "=r"(r0), "=r"(r1), "=r"(r2), "=r"(r3) : "r"(a));
}
__device__ __forceinline__ void mma16816(float* d, const uint32_t* a,
                                         uint32_t b0, uint32_t b1) {
    asm volatile("mma.sync.aligned.m16n8k16.row.col.f32.bf16.bf16.f32 "
                 "{%0,%1,%2,%3}, {%4,%5,%6,%7}, {%8,%9}, {%0,%1,%2,%3};"
                 : "+f"(d[0]), "+f"(d[1]), "+f"(d[2]), "+f"(d[3])
                 : "r"(a[0]), "r"(a[1]), "r"(a[2]), "r"(a[3]), "r"(b0), "r"(b1));
}

// ---------------------------------------------------------------------------
// Prep 1: fp32 -> bf16 hi/lo split (elementwise)
// ---------------------------------------------------------------------------
__global__ void __launch_bounds__(256) split_kernel(const float* __restrict__ x,
                                                    __nv_bfloat16* __restrict__ hi,
                                                    __nv_bfloat16* __restrict__ lo) {
    size_t i = (size_t)blockIdx.x * 256 + threadIdx.x;
    float v = x[i];
    __nv_bfloat16 h = __float2bfloat16(v);
    hi[i] = h;
    lo[i] = __float2bfloat16(v - __bfloat162float(h));
}

// ---------------------------------------------------------------------------
// Prep 2: transpose V [b][s][d] -> Vt [b][d][s], with hi/lo split
// ---------------------------------------------------------------------------
__global__ void __launch_bounds__(256) vtrans_split(const float* __restrict__ V,
                                                    __nv_bfloat16* __restrict__ th,
                                                    __nv_bfloat16* __restrict__ tl) {
    __shared__ float tile[32][33];
    int b = blockIdx.z;
    int s0 = blockIdx.x * 32;
    int d0 = blockIdx.y * 32;
    int tx = threadIdx.x, ty = threadIdx.y;
    const float* Vb = V + (size_t)b * TCTX * DEMB;
#pragma unroll
    for (int i = ty; i < 32; i += 8)
        tile[i][tx] = Vb[(size_t)(s0 + i) * DEMB + d0 + tx];
    __syncthreads();
    size_t base = (size_t)b * DEMB * TCTX;
#pragma unroll
    for (int i = ty; i < 32; i += 8) {
        float v = tile[tx][i];                       // = V[s0+tx][d0+i]
        size_t o = base + (size_t)(d0 + i) * TCTX + s0 + tx;
        __nv_bfloat16 h = __float2bfloat16(v);
        th[o] = h;
        tl[o] = __float2bfloat16(v - __bfloat162float(h));
    }
}

// ---------------------------------------------------------------------------
// GEMM (NT, bf16x3 -> fp32): C[m,n] = sum_k A[m,k]*B[n,k]
// A,B stored row-major over k (lda = ldb = K).
// CTA tile 128x128, warps 2x4 (64x32 each), K-stage 32, double-buffered cp.async.
// __launch_bounds__(256, 2): cap 128 regs so 2 CTAs co-reside per SM
// (regfile 64K: 2*256*128 = 65536). smem 80KB*2 = 160KB < 228KB.
// ---------------------------------------------------------------------------
#define BM 128
#define BN 128
#define BK 32
#define SLD 40                 // padded smem row stride (bf16 elems)
#define TILE_ELEMS (128 * SLD) // 5120
#define GEMM_SMEM_BYTES (2 * 4 * TILE_ELEMS * 2)  // 81,920

__global__ void __launch_bounds__(256, 2) gemm_nt_x3(
    const __nv_bfloat16* __restrict__ Ah, const __nv_bfloat16* __restrict__ Al,
    const __nv_bfloat16* __restrict__ Bh, const __nv_bfloat16* __restrict__ Bl,
    float* __restrict__ C,
    int K, int ldc, size_t sAb, size_t sBb, size_t sCb)
{
    extern __shared__ __nv_bfloat16 sm[];
    // per stage layout: [Ah | Al | Bh | Bl], each TILE_ELEMS
    int tid  = threadIdx.x;
    int lane = tid & 31;
    int w    = tid >> 5;
    int wm   = w >> 2;   // 0..1
    int wn   = w & 3;    // 0..3

    const __nv_bfloat16* gAh = Ah + (size_t)blockIdx.z * sAb + (size_t)(blockIdx.y * BM) * K;
    const __nv_bfloat16* gAl = Al + (size_t)blockIdx.z * sAb + (size_t)(blockIdx.y * BM) * K;
    const __nv_bfloat16* gBh = Bh + (size_t)blockIdx.z * sBb + (size_t)(blockIdx.x * BN) * K;
    const __nv_bfloat16* gBl = Bl + (size_t)blockIdx.z * sBb + (size_t)(blockIdx.x * BN) * K;

    float acc[4][4][4];
#pragma unroll
    for (int i = 0; i < 4; i++)
#pragma unroll
        for (int j = 0; j < 4; j++)
#pragma unroll
            for (int r = 0; r < 4; r++) acc[i][j][r] = 0.f;

    auto load = [&](int stage, int k0) {
        __nv_bfloat16* base = sm + stage * 4 * TILE_ELEMS;
#pragma unroll
        for (int i = 0; i < 2; i++) {
            int c   = tid + i * 256;      // 512 chunks of 16B per 128x32 tile
            int row = c >> 2;
            int cc  = (c & 3) << 3;       // bf16 col offset (8 elems = 16B)
            size_t g = (size_t)row * K + k0 + cc;
            int    s = row * SLD + cc;
            cp16(base + s,                  gAh + g);
            cp16(base + TILE_ELEMS + s,     gAl + g);
            cp16(base + 2 * TILE_ELEMS + s, gBh + g);
            cp16(base + 3 * TILE_ELEMS + s, gBl + g);
        }
        cp_commit();
    };

    load(0, 0);
    int nk = K / BK;
    for (int ko = 0; ko < nk; ko++) {
        int cur = ko & 1;
        if (ko + 1 < nk) { load(cur ^ 1, (ko + 1) * BK); cp_wait1(); }
        else             { cp_wait0(); }
        __syncthreads();

        const __nv_bfloat16* sAh = sm + cur * 4 * TILE_ELEMS;
        const __nv_bfloat16* sAl = sAh + TILE_ELEMS;
        const __nv_bfloat16* sBh = sAh + 2 * TILE_ELEMS;
        const __nv_bfloat16* sBl = sAh + 3 * TILE_ELEMS;

#pragma unroll
        for (int kk = 0; kk < 2; kk++) {
            int g    = lane >> 3;
            int r    = lane & 7;
            int frow = r + (g & 1) * 8;
            int fcol = ((g >> 1) << 3) + kk * 16;

            // A fragments for this k-half (hi + lo): 32 regs live
            uint32_t ah[4][4], al[4][4];
#pragma unroll
            for (int mt = 0; mt < 4; mt++) {
                int off = (wm * 64 + mt * 16 + frow) * SLD + fcol;
                ldsm4(ah[mt][0], ah[mt][1], ah[mt][2], ah[mt][3], sAh + off);
                ldsm4(al[mt][0], al[mt][1], al[mt][2], al[mt][3], sAl + off);
            }
            // B: load one 16-row group (2 n8 fragments) at a time, consume
            // immediately — keeps only 8 B regs live (reg cap = 128).
#pragma unroll
            for (int np = 0; np < 2; np++) {
                int off = (wn * 32 + np * 16 + frow) * SLD + fcol;
                uint32_t h0, h1, h2, h3, l0, l1, l2, l3;
                ldsm4(h0, h1, h2, h3, sBh + off);
                ldsm4(l0, l1, l2, l3, sBl + off);
#pragma unroll
                for (int mt = 0; mt < 4; mt++) {
                    // nt = np*2 : B frag {h0,h2}; nt = np*2+1 : {h1,h3}
                    mma16816(acc[mt][np * 2],     ah[mt], h0, h2);   // hi*hi
                    mma16816(acc[mt][np * 2],     ah[mt], l0, l2);   // hi*lo
                    mma16816(acc[mt][np * 2],     al[mt], h0, h2);   // lo*hi
                    mma16816(acc[mt][np * 2 + 1], ah[mt], h1, h3);
                    mma16816(acc[mt][np * 2 + 1], ah[mt], l1, l3);
                    mma16816(acc[mt][np * 2 + 1], al[mt], h1, h3);
                }
            }
        }
        __syncthreads();
    }

    float* Cb = C + (size_t)blockIdx.z * sCb;
    int mb = blockIdx.y * BM + wm * 64;
    int nb = blockIdx.x * BN + wn * 32;
#pragma unroll
    for (int mt = 0; mt < 4; mt++) {
        int row = mb + mt * 16 + (lane >> 2);
#pragma unroll
        for (int nt = 0; nt < 4; nt++) {
            int col = nb + nt * 8 + ((lane & 3) << 1);
            float2 v0; v0.x = acc[mt][nt][0]; v0.y = acc[mt][nt][1];
            float2 v1; v1.x = acc[mt][nt][2]; v1.y = acc[mt][nt][3];
            *(float2*)(Cb + (size_t)row * ldc + col)       = v0;
            *(float2*)(Cb + (size_t)(row + 8) * ldc + col) = v1;
        }
    }
}

// ---------------------------------------------------------------------------
// Softmax over rows of S (scale applied here), output hi/lo bf16 probs
// One CTA (256 threads) per row of 4096.
// ---------------------------------------------------------------------------
__global__ void __launch_bounds__(256) softmax_kernel(const float* __restrict__ S,
                                                      __nv_bfloat16* __restrict__ Ph,
                                                      __nv_bfloat16* __restrict__ Pl) {
    __shared__ float redm[8], reds[8];
    size_t row = blockIdx.x;
    const float* s = S + row * (size_t)TCTX;
    int tid = threadIdx.x;

    float x[16];
    float m = -1e30f;
#pragma unroll
    for (int i = 0; i < 16; i++) {
        x[i] = s[tid + (i << 8)] * SCALE;
        m = fmaxf(m, x[i]);
    }
#pragma unroll
    for (int o = 16; o > 0; o >>= 1) m = fmaxf(m, __shfl_xor_sync(0xffffffffu, m, o));
    if ((tid & 31) == 0) redm[tid >> 5] = m;
    __syncthreads();
    float M = redm[0];
#pragma unroll
    for (int i = 1; i < 8; i++) M = fmaxf(M, redm[i]);

    float sum = 0.f;
#pragma unroll
    for (int i = 0; i < 16; i++) { x[i] = __expf(x[i] - M); sum += x[i]; }
#pragma unroll
    for (int o = 16; o > 0; o >>= 1) sum += __shfl_xor_sync(0xffffffffu, sum, o);
    if ((tid & 31) == 0) reds[tid >> 5] = sum;
    __syncthreads();
    float tot = 0.f;
#pragma unroll
    for (int i = 0; i < 8; i++) tot += reds[i];
    float inv = 1.f / tot;

    __nv_bfloat16* ph = Ph + row * (size_t)TCTX;
    __nv_bfloat16* pl = Pl + row * (size_t)TCTX;
#pragma unroll
    for (int i = 0; i < 16; i++) {
        float p = x[i] * inv;
        __nv_bfloat16 h = __float2bfloat16(p);
        ph[tid + (i << 8)] = h;
        pl[tid + (i << 8)] = __float2bfloat16(p - __bfloat162float(h));
    }
}

// ---------------------------------------------------------------------------
// Launch
// ---------------------------------------------------------------------------
extern "C" void kernel_launch(void* const* d_in, const int* in_sizes, int n_in,
                              void* d_out, int out_size) {
    const float* q = (const float*)d_in[0];
    const float* k = (const float*)d_in[1];
    const float* v = (const float*)d_in[2];
    float* out = (float*)d_out;

    __nv_bfloat16 *Qh, *Ql, *Kh, *Kl, *Vth, *Vtl, *Ph, *Pl;
    float* S;
    cudaGetSymbolAddress((void**)&Qh,  g_Qh);
    cudaGetSymbolAddress((void**)&Ql,  g_Ql);
    cudaGetSymbolAddress((void**)&Kh,  g_Kh);
    cudaGetSymbolAddress((void**)&Kl,  g_Kl);
    cudaGetSymbolAddress((void**)&Vth, g_Vth);
    cudaGetSymbolAddress((void**)&Vtl, g_Vtl);
    cudaGetSymbolAddress((void**)&S,   g_S);
    cudaGetSymbolAddress((void**)&Ph,  g_Ph);
    cudaGetSymbolAddress((void**)&Pl,  g_Pl);

    cudaFuncSetAttribute(gemm_nt_x3, cudaFuncAttributeMaxDynamicSharedMemorySize,
                         GEMM_SMEM_BYTES);

    // Prep: split Q, K; transpose+split V
    int nblk = (int)(QKV_ELEMS / 256);
    split_kernel<<<nblk, 256>>>(q, Qh, Ql);
    split_kernel<<<nblk, 256>>>(k, Kh, Kl);
    vtrans_split<<<dim3(TCTX / 32, DEMB / 32, NB), dim3(32, 8)>>>(v, Vth, Vtl);

    // GEMM1: S[b] = Q[b] * K[b]^T   (M=N=4096, K=512)
    gemm_nt_x3<<<dim3(TCTX / BN, TCTX / BM, NB), 256, GEMM_SMEM_BYTES>>>(
        Qh, Ql, Kh, Kl, S,
        DEMB, TCTX,
        (size_t)TCTX * DEMB, (size_t)TCTX * DEMB, (size_t)TCTX * TCTX);

    // Softmax rows -> P hi/lo
    softmax_kernel<<<NB * TCTX, 256>>>(S, Ph, Pl);

    // GEMM2: O[b] = P[b] * V[b]    (M=4096, N=512, K=4096; B = V^T rows = d)
    gemm_nt_x3<<<dim3(DEMB / BN, TCTX / BM, NB), 256, GEMM_SMEM_BYTES>>>(
        Ph, Pl, Vth, Vtl, out,
        TCTX, DEMB,
        (size_t)TCTX * TCTX, (size_t)DEMB * TCTX, (size_t)TCTX * DEMB);
}

// round 17
// speedup vs baseline: 1.1143x; 1.0008x over previous
#include <cuda_runtime.h>
#include <cuda_bf16.h>
#include <cstdint>
#include <cstddef>

// Problem constants
#define NB   4
#define TCTX 4096
#define DEMB 512
#define SCALE 0.125f   // 1/sqrt(512/8) = 1/8

static constexpr size_t QKV_ELEMS = (size_t)NB * TCTX * DEMB;   // 8,388,608
static constexpr size_t ATT_ELEMS = (size_t)NB * TCTX * TCTX;   // 67,108,864

// Scratch (static __device__ arrays — allocation-free per harness rules)
__device__ __align__(128) __nv_bfloat16 g_Qh[QKV_ELEMS];
__device__ __align__(128) __nv_bfloat16 g_Ql[QKV_ELEMS];
__device__ __align__(128) __nv_bfloat16 g_Kh[QKV_ELEMS];
__device__ __align__(128) __nv_bfloat16 g_Kl[QKV_ELEMS];
__device__ __align__(128) __nv_bfloat16 g_Vth[QKV_ELEMS];   // V transposed [b][d][s]
__device__ __align__(128) __nv_bfloat16 g_Vtl[QKV_ELEMS];
__device__ __align__(128) float         g_S [ATT_ELEMS];    // logits (unscaled)
__device__ __align__(128) __nv_bfloat16 g_Ph[ATT_ELEMS];    // softmax probs hi
__device__ __align__(128) __nv_bfloat16 g_Pl[ATT_ELEMS];    // softmax probs lo

// ---------------------------------------------------------------------------
// PTX helpers
// ---------------------------------------------------------------------------
__device__ __forceinline__ void cp16(void* dst_smem, const void* src_gmem) {
    uint32_t d = (uint32_t)__cvta_generic_to_shared(dst_smem);
    size_t   s = __cvta_generic_to_global(src_gmem);
    asm volatile("cp.async.cg.shared.global [%0], [%1], 16;" :: "r"(d), "l"(s) : "memory");
}
__device__ __forceinline__ void cp_commit() {
    asm volatile("cp.async.commit_group;" ::: "memory");
}
__device__ __forceinline__ void cp_wait1() {
    asm volatile("cp.async.wait_group 1;" ::: "memory");
}
__device__ __forceinline__ void cp_wait0() {
    asm volatile("cp.async.wait_group 0;" ::: "memory");
}
__device__ __forceinline__ void ldsm4(uint32_t& r0, uint32_t& r1, uint32_t& r2, uint32_t& r3,
                                      const void* p) {
    uint32_t a = (uint32_t)__cvta_generic_to_shared((void*)p);
    asm volatile("ldmatrix.sync.aligned.m8n8.x4.shared.b16 {%0,%1,%2,%3}, [%4];"
                 : "=r"(r0), "=r"(r1), "=r"(r2), "=r"(r3) : "r"(a));
}
// NOTE: non-volatile on purpose — register dataflow carries all dependencies,
// and ptxas is free to interleave independent HMMAs to hide RAW latency.
__device__ __forceinline__ void mma16816(float* d, const uint32_t* a,
                                         uint32_t b0, uint32_t b1) {
    asm("mma.sync.aligned.m16n8k16.row.col.f32.bf16.bf16.f32 "
        "{%0,%1,%2,%3}, {%4,%5,%6,%7}, {%8,%9}, {%0,%1,%2,%3};"
        : "+f"(d[0]), "+f"(d[1]), "+f"(d[2]), "+f"(d[3])
        : "r"(a[0]), "r"(a[1]), "r"(a[2]), "r"(a[3]), "r"(b0), "r"(b1));
}

// ---------------------------------------------------------------------------
// Prep 1: fp32 -> bf16 hi/lo split (elementwise)
// ---------------------------------------------------------------------------
__global__ void __launch_bounds__(256) split_kernel(const float* __restrict__ x,
                                                    __nv_bfloat16* __restrict__ hi,
                                                    __nv_bfloat16* __restrict__ lo) {
    size_t i = (size_t)blockIdx.x * 256 + threadIdx.x;
    float v = x[i];
    __nv_bfloat16 h = __float2bfloat16(v);
    hi[i] = h;
    lo[i] = __float2bfloat16(v - __bfloat162float(h));
}

// ---------------------------------------------------------------------------
// Prep 2: transpose V [b][s][d] -> Vt [b][d][s], with hi/lo split
// ---------------------------------------------------------------------------
__global__ void __launch_bounds__(256) vtrans_split(const float* __restrict__ V,
                                                    __nv_bfloat16* __restrict__ th,
                                                    __nv_bfloat16* __restrict__ tl) {
    __shared__ float tile[32][33];
    int b = blockIdx.z;
    int s0 = blockIdx.x * 32;
    int d0 = blockIdx.y * 32;
    int tx = threadIdx.x, ty = threadIdx.y;
    const float* Vb = V + (size_t)b * TCTX * DEMB;
#pragma unroll
    for (int i = ty; i < 32; i += 8)
        tile[i][tx] = Vb[(size_t)(s0 + i) * DEMB + d0 + tx];
    __syncthreads();
    size_t base = (size_t)b * DEMB * TCTX;
#pragma unroll
    for (int i = ty; i < 32; i += 8) {
        float v = tile[tx][i];                       // = V[s0+tx][d0+i]
        size_t o = base + (size_t)(d0 + i) * TCTX + s0 + tx;
        __nv_bfloat16 h = __float2bfloat16(v);
        th[o] = h;
        tl[o] = __float2bfloat16(v - __bfloat162float(h));
    }
}

// ---------------------------------------------------------------------------
// GEMM (NT, bf16x3 -> fp32): C[m,n] = sum_k A[m,k]*B[n,k]
// A,B stored row-major over k (lda = ldb = K).
// CTA tile 128x128, warps 2x4 (64x32 each), K-stage 32, double-buffered cp.async.
// __launch_bounds__(256, 2): cap 128 regs -> 2 CTAs/SM.
// Inner loop issues MMAs pass-major so same-accumulator RAW distance = 8.
// ---------------------------------------------------------------------------
#define BM 128
#define BN 128
#define BK 32
#define SLD 40                 // padded smem row stride (bf16 elems)
#define TILE_ELEMS (128 * SLD) // 5120
#define GEMM_SMEM_BYTES (2 * 4 * TILE_ELEMS * 2)  // 81,920

__global__ void __launch_bounds__(256, 2) gemm_nt_x3(
    const __nv_bfloat16* __restrict__ Ah, const __nv_bfloat16* __restrict__ Al,
    const __nv_bfloat16* __restrict__ Bh, const __nv_bfloat16* __restrict__ Bl,
    float* __restrict__ C,
    int K, int ldc, size_t sAb, size_t sBb, size_t sCb)
{
    extern __shared__ __nv_bfloat16 sm[];
    // per stage layout: [Ah | Al | Bh | Bl], each TILE_ELEMS
    int tid  = threadIdx.x;
    int lane = tid & 31;
    int w    = tid >> 5;
    int wm   = w >> 2;   // 0..1
    int wn   = w & 3;    // 0..3

    const __nv_bfloat16* gAh = Ah + (size_t)blockIdx.z * sAb + (size_t)(blockIdx.y * BM) * K;
    const __nv_bfloat16* gAl = Al + (size_t)blockIdx.z * sAb + (size_t)(blockIdx.y * BM) * K;
    const __nv_bfloat16* gBh = Bh + (size_t)blockIdx.z * sBb + (size_t)(blockIdx.x * BN) * K;
    const __nv_bfloat16* gBl = Bl + (size_t)blockIdx.z * sBb + (size_t)(blockIdx.x * BN) * K;

    float acc[4][4][4];
#pragma unroll
    for (int i = 0; i < 4; i++)
#pragma unroll
        for (int j = 0; j < 4; j++)
#pragma unroll
            for (int r = 0; r < 4; r++) acc[i][j][r] = 0.f;

    auto load = [&](int stage, int k0) {
        __nv_bfloat16* base = sm + stage * 4 * TILE_ELEMS;
#pragma unroll
        for (int i = 0; i < 2; i++) {
            int c   = tid + i * 256;      // 512 chunks of 16B per 128x32 tile
            int row = c >> 2;
            int cc  = (c & 3) << 3;       // bf16 col offset (8 elems = 16B)
            size_t g = (size_t)row * K + k0 + cc;
            int    s = row * SLD + cc;
            cp16(base + s,                  gAh + g);
            cp16(base + TILE_ELEMS + s,     gAl + g);
            cp16(base + 2 * TILE_ELEMS + s, gBh + g);
            cp16(base + 3 * TILE_ELEMS + s, gBl + g);
        }
        cp_commit();
    };

    load(0, 0);
    int nk = K / BK;
    for (int ko = 0; ko < nk; ko++) {
        int cur = ko & 1;
        if (ko + 1 < nk) { load(cur ^ 1, (ko + 1) * BK); cp_wait1(); }
        else             { cp_wait0(); }
        __syncthreads();

        const __nv_bfloat16* sAh = sm + cur * 4 * TILE_ELEMS;
        const __nv_bfloat16* sAl = sAh + TILE_ELEMS;
        const __nv_bfloat16* sBh = sAh + 2 * TILE_ELEMS;
        const __nv_bfloat16* sBl = sAh + 3 * TILE_ELEMS;

#pragma unroll
        for (int kk = 0; kk < 2; kk++) {
            int g    = lane >> 3;
            int r    = lane & 7;
            int frow = r + (g & 1) * 8;
            int fcol = ((g >> 1) << 3) + kk * 16;

            // A fragments for this k-half (hi + lo): 32 regs live
            uint32_t ah[4][4], al[4][4];
#pragma unroll
            for (int mt = 0; mt < 4; mt++) {
                int off = (wm * 64 + mt * 16 + frow) * SLD + fcol;
                ldsm4(ah[mt][0], ah[mt][1], ah[mt][2], ah[mt][3], sAh + off);
                ldsm4(al[mt][0], al[mt][1], al[mt][2], al[mt][3], sAl + off);
            }
            // B: one 16-row group (8 regs live), consumed pass-major:
            // all 8 tiles of hi*hi, then hi*lo, then lo*hi.
            // Same-acc RAW distance = 8 HMMAs (was 1).
#pragma unroll
            for (int np = 0; np < 2; np++) {
                int off = (wn * 32 + np * 16 + frow) * SLD + fcol;
                uint32_t h0, h1, h2, h3, l0, l1, l2, l3;
                ldsm4(h0, h1, h2, h3, sBh + off);
                ldsm4(l0, l1, l2, l3, sBl + off);
                // pass 0: hi * hi
#pragma unroll
                for (int mt = 0; mt < 4; mt++) {
                    mma16816(acc[mt][np * 2],     ah[mt], h0, h2);
                    mma16816(acc[mt][np * 2 + 1], ah[mt], h1, h3);
                }
                // pass 1: hi * lo
#pragma unroll
                for (int mt = 0; mt < 4; mt++) {
                    mma16816(acc[mt][np * 2],     ah[mt], l0, l2);
                    mma16816(acc[mt][np * 2 + 1], ah[mt], l1, l3);
                }
                // pass 2: lo * hi
#pragma unroll
                for (int mt = 0; mt < 4; mt++) {
                    mma16816(acc[mt][np * 2],     al[mt], h0, h2);
                    mma16816(acc[mt][np * 2 + 1], al[mt], h1, h3);
                }
            }
        }
        __syncthreads();
    }

    float* Cb = C + (size_t)blockIdx.z * sCb;
    int mb = blockIdx.y * BM + wm * 64;
    int nb = blockIdx.x * BN + wn * 32;
#pragma unroll
    for (int mt = 0; mt < 4; mt++) {
        int row = mb + mt * 16 + (lane >> 2);
#pragma unroll
        for (int nt = 0; nt < 4; nt++) {
            int col = nb + nt * 8 + ((lane & 3) << 1);
            float2 v0; v0.x = acc[mt][nt][0]; v0.y = acc[mt][nt][1];
            float2 v1; v1.x = acc[mt][nt][2]; v1.y = acc[mt][nt][3];
            *(float2*)(Cb + (size_t)row * ldc + col)       = v0;
            *(float2*)(Cb + (size_t)(row + 8) * ldc + col) = v1;
        }
    }
}

// ---------------------------------------------------------------------------
// Softmax over rows of S (scale applied here), output hi/lo bf16 probs
// One CTA (256 threads) per row of 4096.
// ---------------------------------------------------------------------------
__global__ void __launch_bounds__(256) softmax_kernel(const float* __restrict__ S,
                                                      __nv_bfloat16* __restrict__ Ph,
                                                      __nv_bfloat16* __restrict__ Pl) {
    __shared__ float redm[8], reds[8];
    size_t row = blockIdx.x;
    const float* s = S + row * (size_t)TCTX;
    int tid = threadIdx.x;

    float x[16];
    float m = -1e30f;
#pragma unroll
    for (int i = 0; i < 16; i++) {
        x[i] = s[tid + (i << 8)] * SCALE;
        m = fmaxf(m, x[i]);
    }
#pragma unroll
    for (int o = 16; o > 0; o >>= 1) m = fmaxf(m, __shfl_xor_sync(0xffffffffu, m, o));
    if ((tid & 31) == 0) redm[tid >> 5] = m;
    __syncthreads();
    float M = redm[0];
#pragma unroll
    for (int i = 1; i < 8; i++) M = fmaxf(M, redm[i]);

    float sum = 0.f;
#pragma unroll
    for (int i = 0; i < 16; i++) { x[i] = __expf(x[i] - M); sum += x[i]; }
#pragma unroll
    for (int o = 16; o > 0; o >>= 1) sum += __shfl_xor_sync(0xffffffffu, sum, o);
    if ((tid & 31) == 0) reds[tid >> 5] = sum;
    __syncthreads();
    float tot = 0.f;
#pragma unroll
    for (int i = 0; i < 8; i++) tot += reds[i];
    float inv = 1.f / tot;

    __nv_bfloat16* ph = Ph + row * (size_t)TCTX;
    __nv_bfloat16* pl = Pl + row * (size_t)TCTX;
#pragma unroll
    for (int i = 0; i < 16; i++) {
        float p = x[i] * inv;
        __nv_bfloat16 h = __float2bfloat16(p);
        ph[tid + (i << 8)] = h;
        pl[tid + (i << 8)] = __float2bfloat16(p - __bfloat162float(h));
    }
}

// ---------------------------------------------------------------------------
// Launch
// ---------------------------------------------------------------------------
extern "C" void kernel_launch(void* const* d_in, const int* in_sizes, int n_in,
                              void* d_out, int out_size) {
    const float* q = (const float*)d_in[0];
    const float* k = (const float*)d_in[1];
    const float* v = (const float*)d_in[2];
    float* out = (float*)d_out;

    __nv_bfloat16 *Qh, *Ql, *Kh, *Kl, *Vth, *Vtl, *Ph, *Pl;
    float* S;
    cudaGetSymbolAddress((void**)&Qh,  g_Qh);
    cudaGetSymbolAddress((void**)&Ql,  g_Ql);
    cudaGetSymbolAddress((void**)&Kh,  g_Kh);
    cudaGetSymbolAddress((void**)&Kl,  g_Kl);
    cudaGetSymbolAddress((void**)&Vth, g_Vth);
    cudaGetSymbolAddress((void**)&Vtl, g_Vtl);
    cudaGetSymbolAddress((void**)&S,   g_S);
    cudaGetSymbolAddress((void**)&Ph,  g_Ph);
    cudaGetSymbolAddress((void**)&Pl,  g_Pl);

    cudaFuncSetAttribute(gemm_nt_x3, cudaFuncAttributeMaxDynamicSharedMemorySize,
                         GEMM_SMEM_BYTES);

    // Prep: split Q, K; transpose+split V
    int nblk = (int)(QKV_ELEMS / 256);
    split_kernel<<<nblk, 256>>>(q, Qh, Ql);
    split_kernel<<<nblk, 256>>>(k, Kh, Kl);
    vtrans_split<<<dim3(TCTX / 32, DEMB / 32, NB), dim3(32, 8)>>>(v, Vth, Vtl);

    // GEMM1: S[b] = Q[b] * K[b]^T   (M=N=4096, K=512)
    gemm_nt_x3<<<dim3(TCTX / BN, TCTX / BM, NB), 256, GEMM_SMEM_BYTES>>>(
        Qh, Ql, Kh, Kl, S,
        DEMB, TCTX,
        (size_t)TCTX * DEMB, (size_t)TCTX * DEMB, (size_t)TCTX * TCTX);

    // Softmax rows -> P hi/lo
    softmax_kernel<<<NB * TCTX, 256>>>(S, Ph, Pl);

    // GEMM2: O[b] = P[b] * V[b]    (M=4096, N=512, K=4096; B = V^T rows = d)
    gemm_nt_x3<<<dim3(DEMB / BN, TCTX / BM, NB), 256, GEMM_SMEM_BYTES>>>(
        Ph, Pl, Vth, Vtl, out,
        TCTX, DEMB,
        (size_t)TCTX * TCTX, (size_t)DEMB * TCTX, (size_t)TCTX * DEMB);
}